// round 6
// baseline (speedup 1.0000x reference)
#include <cuda_runtime.h>
#include <cstddef>

// ---------------------------------------------------------------------------
// Problem constants
// ---------------------------------------------------------------------------
#define HW    16384            // 128*128
#define NCHW  4194304          // 4*64*16384
#define WSZ   102400           // 64*25*64 (per-layer weight count)

typedef unsigned long long u64;

// ---------------------------------------------------------------------------
// Scratch: __device__ globals (module-load allocation; no cudaMalloc)
// ---------------------------------------------------------------------------
__device__ float g_A[NCHW];                 // ping
__device__ float g_B[NCHW];                 // pong
__device__ float g_T[3ull * NCHW];          // t0..t2 (t3 never read)
__device__ u64   g_wfd[3 * WSZ];            // fwd weights, lane-duplicated f32x2: [l][ci][uv][co]
__device__ u64   g_wbd[3 * WSZ];            // bwd weights (transposed+flipped), dup'd
__device__ u64   g_w0d[25 * 64];            // conv0 weights dup'd: [uv][co]
__device__ float g_w0b[64 * 25];            // final convT weights [a][ky][kx] (flipped)
__device__ float g_actp[4 * 64 * 80];       // padded act tables: [l][c][80], data at +8

// ---------------------------------------------------------------------------
// Packed f32x2 helpers (sm_100a)
// ---------------------------------------------------------------------------
__device__ __forceinline__ u64 pk2(float lo, float hi) {
    u64 r;
    asm("mov.b64 %0, {%1, %2};" : "=l"(r) : "f"(lo), "f"(hi));
    return r;
}
__device__ __forceinline__ void fma2(u64& d, u64 a, u64 b) {
    asm("fma.rn.f32x2 %0, %1, %2, %0;" : "+l"(d) : "l"(a), "l"(b));
}
__device__ __forceinline__ float2 upk(u64 v) {
    float2 r;
    asm("mov.b64 {%0, %1}, %2;" : "=f"(r.x), "=f"(r.y) : "l"(v));
    return r;
}

// ---------------------------------------------------------------------------
// RBF mixture activation, windowed (|k|<=6) stable recurrence.
//   f(v) = sum_p w[p] exp(-(v-mu_p)^2/200),  mu_p = -310 + 10 p
//   exp(-(d0-10k)^2/200) = E0 * a^k * e^{-k^2/2},  E0=e^{-d0^2/200}, a=e^{d0/10}
// wrow points at p=0 of a zero-padded row (8 left / 9 right) -> branch free.
// ---------------------------------------------------------------------------
__device__ __forceinline__ float act_fwd(float v, const float* __restrict__ wrow) {
    float pf = rintf((v + 310.f) * 0.1f);
    pf = fminf(fmaxf(pf, 0.f), 62.f);
    float d0 = v + 310.f - 10.f * pf;
    d0 = fminf(fmaxf(d0, -55.f), 55.f);
    float a  = __expf(0.1f * d0);
    float ai = __expf(-0.1f * d0);
    float E0 = __expf(-0.005f * d0 * d0);
    const float* w = wrow + (int)pf;
    const float CK[7] = {0.f, 0.60653066f, 0.22313016f, 0.082084999f,
                         0.030197383f, 0.011108997f, 0.0040867714f};
    float s = w[0];
    float up = 1.f, un = 1.f;
#pragma unroll
    for (int k = 1; k <= 6; k++) {
        up *= a  * CK[k];
        un *= ai * CK[k];
        s += w[k] * up + w[-k] * un;
    }
    return E0 * s;
}

// f'(v) = -(1/100) * E0 * (d0*s - 10*s1),  s1 = sum_k k w_k u_k
__device__ __forceinline__ float act_grad(float v, const float* __restrict__ wrow) {
    float pf = rintf((v + 310.f) * 0.1f);
    pf = fminf(fmaxf(pf, 0.f), 62.f);
    float d0 = v + 310.f - 10.f * pf;
    d0 = fminf(fmaxf(d0, -55.f), 55.f);
    float a  = __expf(0.1f * d0);
    float ai = __expf(-0.1f * d0);
    float E0 = __expf(-0.005f * d0 * d0);
    const float* w = wrow + (int)pf;
    const float CK[7] = {0.f, 0.60653066f, 0.22313016f, 0.082084999f,
                         0.030197383f, 0.011108997f, 0.0040867714f};
    float s = w[0], s1 = 0.f;
    float up = 1.f, un = 1.f;
#pragma unroll
    for (int k = 1; k <= 6; k++) {
        up *= a  * CK[k];
        un *= ai * CK[k];
        float tp = w[k]  * up;
        float tm = w[-k] * un;
        s  += tp + tm;
        s1 += (float)k * (tp - tm);
    }
    return -0.01f * E0 * (d0 * s - 10.f * s1);
}

// ---------------------------------------------------------------------------
// Weight / table prep (duplicate each weight into both f32x2 lanes)
// ---------------------------------------------------------------------------
__device__ __forceinline__ u64 dupf(float v) {
    u64 u = (u64)__float_as_uint(v);
    return u | (u << 32);
}

__global__ void prep_kernel(const float* __restrict__ f0,
                            const float* __restrict__ fr,
                            const float* __restrict__ actw) {
    int idx = blockIdx.x * 256 + threadIdx.x;
    if (idx < 3 * WSZ) {
        int co = idx & 63;
        int r  = idx >> 6;
        int kx = r % 5; r /= 5;
        int ky = r % 5; r /= 5;
        int ci = r & 63;
        int l  = r >> 6;
        // fwd: wfd[l][ci][ky][kx][co] = fr[l][co][ci][ky][kx]
        g_wfd[idx] = dupf(fr[(((l * 64 + co) * 64 + ci) * 25) + ky * 5 + kx]);
        // bwd (conv_t as zero-padded corr): wbd[l][a][ky][kx][b] = fr[l][a][b][4-ky][4-kx]
        g_wbd[idx] = dupf(fr[(((l * 64 + ci) * 64 + co) * 25) + (4 - ky) * 5 + (4 - kx)]);
    }
    if (idx < 1600) {
        int co = idx & 63;
        int r  = idx >> 6;
        int kx = r % 5, ky = r / 5;
        g_w0d[idx] = dupf(f0[co * 25 + ky * 5 + kx]);     // [ky][kx][co]
        int a = idx / 25, q = idx % 25;
        int u = q / 5, v = q % 5;
        g_w0b[idx] = f0[a * 25 + (4 - u) * 5 + (4 - v)];  // [a][u][v], flipped
    }
    if (idx < 4 * 64 * 80) {
        int q  = (idx % 80) - 8;
        int lc = idx / 80;
        g_actp[idx] = (q >= 0 && q < 63) ? actw[lc * 63 + q] : 0.f;
    }
}

// ---------------------------------------------------------------------------
// Main conv kernel. Tile 32x8 px, 256 threads; thread = 8 px (4 row-pairs)
// x 8 co, accumulated as 32 packed f32x2 (fma.rn.f32x2 -> 2x fp32 rate).
// Weights: lane-duplicated [ci][uv][co] -> warp-uniform LDG.128 of packed ops.
// FWD: replication pad, +bias, store conv (tout if STORE_T) and act (out).
// BWD: zero pad, epilogue gate by act_grad(tg), store to out.
// ---------------------------------------------------------------------------
template <bool BWD, int NCI, bool STORE_T>
__global__ __launch_bounds__(256, 2)
void conv_kernel(const float* __restrict__ in, float inscale,
                 const u64* __restrict__ w,
                 const float* __restrict__ bias,
                 const float* __restrict__ actp,
                 const float* __restrict__ tg,
                 float* __restrict__ tout,
                 float* __restrict__ out) {
    __shared__ float s_act[64 * 80];
    __shared__ float s_in[12 * 36];
    const int tid = threadIdx.x;
    const int x   = tid & 31;
    const int wid = tid >> 5;                  // co octet
    const int n   = blockIdx.z;
    const int tx0 = blockIdx.x * 32, ty0 = blockIdx.y * 8;

    for (int i = tid; i < 64 * 80; i += 256) s_act[i] = actp[i];

    u64 acc[32];
#pragma unroll
    for (int i = 0; i < 32; i++) acc[i] = 0ull;

    for (int ci = 0; ci < NCI; ci++) {
        __syncthreads();                        // also covers s_act on first iter
        const float* ip = in + ((size_t)(n * NCI + ci)) * HW;
        for (int i = tid; i < 432; i += 256) {
            int py = i / 36, px = i - py * 36;
            int gy = ty0 + py - 2, gx = tx0 + px - 2;
            float v;
            if (BWD) {
                v = (gy >= 0 && gy < 128 && gx >= 0 && gx < 128) ? ip[gy * 128 + gx] : 0.f;
            } else {
                gy = min(max(gy, 0), 127);
                gx = min(max(gx, 0), 127);
                v = ip[gy * 128 + gx] * inscale;
            }
            s_in[i] = v;
        }
        __syncthreads();
        const u64* wp = w + ci * 1600 + wid * 8;
#pragma unroll
        for (int u = 0; u < 5; u++) {
#pragma unroll
            for (int v = 0; v < 5; v++) {
                const ulonglong2* wq = reinterpret_cast<const ulonglong2*>(wp + (u * 5 + v) * 64);
                ulonglong2 wA = __ldg(wq);
                ulonglong2 wB = __ldg(wq + 1);
                ulonglong2 wC = __ldg(wq + 2);
                ulonglong2 wD = __ldg(wq + 3);
                u64 ivp[4];
#pragma unroll
                for (int p = 0; p < 4; p++)
                    ivp[p] = pk2(s_in[(2 * p     + u) * 36 + x + v],
                                 s_in[(2 * p + 1 + u) * 36 + x + v]);
#pragma unroll
                for (int p = 0; p < 4; p++) {
                    fma2(acc[p * 8 + 0], ivp[p], wA.x);
                    fma2(acc[p * 8 + 1], ivp[p], wA.y);
                    fma2(acc[p * 8 + 2], ivp[p], wB.x);
                    fma2(acc[p * 8 + 3], ivp[p], wB.y);
                    fma2(acc[p * 8 + 4], ivp[p], wC.x);
                    fma2(acc[p * 8 + 5], ivp[p], wC.y);
                    fma2(acc[p * 8 + 6], ivp[p], wD.x);
                    fma2(acc[p * 8 + 7], ivp[p], wD.y);
                }
            }
        }
    }

    // Epilogue
#pragma unroll
    for (int c = 0; c < 8; c++) {
        const int co = wid * 8 + c;
        const float* wrow = &s_act[co * 80 + 8];
        const float b = BWD ? 0.f : bias[co];
        size_t base = ((size_t)(n * 64 + co)) * HW + (size_t)ty0 * 128 + tx0 + x;
#pragma unroll
        for (int p = 0; p < 4; p++) {
            float2 vv = upk(acc[p * 8 + c]);
            size_t i0 = base + (size_t)(2 * p) * 128;
            size_t i1 = i0 + 128;
            float v0 = vv.x + b;
            float v1 = vv.y + b;
            if (BWD) {
                out[i0] = v0 * act_grad(tg[i0], wrow);
                out[i1] = v1 * act_grad(tg[i1], wrow);
            } else {
                if (STORE_T) { tout[i0] = v0; tout[i1] = v1; }
                out[i0] = act_fwd(v0, wrow);
                out[i1] = act_fwd(v1, wrow);
            }
        }
    }
}

// ---------------------------------------------------------------------------
// Final: r = crop(conv_t(in, f0)) (64->1, zero pad), out = x - r/255 - e^lam*(x-y)
// ci chunked by 4.
// ---------------------------------------------------------------------------
__global__ __launch_bounds__(256)
void final_kernel(const float* __restrict__ in,
                  const float* __restrict__ xin,
                  const float* __restrict__ yin,
                  const float* __restrict__ lam,
                  float* __restrict__ out) {
    __shared__ float s_w[1600];
    __shared__ float s_in[4 * 432];
    const int tid = threadIdx.x;
    const int x   = tid & 31;
    const int yy  = tid >> 5;
    const int n   = blockIdx.z;
    const int tx0 = blockIdx.x * 32, ty0 = blockIdx.y * 8;

    for (int i = tid; i < 1600; i += 256) s_w[i] = g_w0b[i];

    float acc = 0.f;
    for (int c0 = 0; c0 < 64; c0 += 4) {
        __syncthreads();
        for (int i = tid; i < 4 * 432; i += 256) {
            int cc = i / 432, j = i - cc * 432;
            int py = j / 36, px = j - py * 36;
            int gy = ty0 + py - 2, gx = tx0 + px - 2;
            const float* ip = in + ((size_t)(n * 64 + c0 + cc)) * HW;
            s_in[i] = (gy >= 0 && gy < 128 && gx >= 0 && gx < 128) ? ip[gy * 128 + gx] : 0.f;
        }
        __syncthreads();
#pragma unroll
        for (int cc = 0; cc < 4; cc++) {
            const float* wp  = &s_w[(c0 + cc) * 25];
            const float* pin = s_in + cc * 432;
#pragma unroll
            for (int u = 0; u < 5; u++)
#pragma unroll
                for (int v = 0; v < 5; v++)
                    acc += pin[(yy + u) * 36 + x + v] * wp[u * 5 + v];
        }
    }
    size_t idx = (size_t)n * HW + (size_t)(ty0 + yy) * 128 + tx0 + x;
    float xv = xin[idx], yv = yin[idx];
    float el = __expf(lam[0]);
    out[idx] = xv - acc * (1.f / 255.f) - el * (xv - yv);
}

// ---------------------------------------------------------------------------
// Launch
// ---------------------------------------------------------------------------
extern "C" void kernel_launch(void* const* d_in, const int* in_sizes, int n_in,
                              void* d_out, int out_size) {
    const float *x = nullptr, *y = nullptr, *lam = nullptr, *f0 = nullptr,
                *fr = nullptr, *bias = nullptr, *actw = nullptr;
    for (int i = 0; i < n_in; i++) {
        const float* p = (const float*)d_in[i];
        switch (in_sizes[i]) {
            case 65536: if (!x) x = p; else y = p; break;   // x first, y second (metadata order)
            case 1:      lam  = p; break;
            case 1600:   f0   = p; break;
            case 307200: fr   = p; break;
            case 256:    bias = p; break;
            case 16128:  actw = p; break;
            default: break;
        }
    }

    void *pA, *pB, *pT, *pwf, *pwb, *pw0, *pact;
    cudaGetSymbolAddress(&pA, g_A);
    cudaGetSymbolAddress(&pB, g_B);
    cudaGetSymbolAddress(&pT, g_T);
    cudaGetSymbolAddress(&pwf, g_wfd);
    cudaGetSymbolAddress(&pwb, g_wbd);
    cudaGetSymbolAddress(&pw0, g_w0d);
    cudaGetSymbolAddress(&pact, g_actp);
    float* A   = (float*)pA;
    float* B   = (float*)pB;
    float* T   = (float*)pT;
    u64*   wf  = (u64*)pwf;
    u64*   wb  = (u64*)pwb;
    u64*   w0  = (u64*)pw0;
    float* act = (float*)pact;

    dim3 grid(4, 16, 4), blk(256);

    prep_kernel<<<1200, 256>>>(f0, fr, actw);

    // forward: conv0 (1->64, x255) then layers 1..3 (t3 never read -> no store)
    conv_kernel<false, 1,  true ><<<grid, blk>>>(x, 255.f, w0,           bias,       act,            nullptr,          T,                A);
    conv_kernel<false, 64, true ><<<grid, blk>>>(A, 1.f,   wf,           bias + 64,  act + 5120,     nullptr,          T + (size_t)NCHW, B);
    conv_kernel<false, 64, true ><<<grid, blk>>>(B, 1.f,   wf + WSZ,     bias + 128, act + 2 * 5120, nullptr,          T + 2ull * NCHW,  A);
    conv_kernel<false, 64, false><<<grid, blk>>>(A, 1.f,   wf + 2 * WSZ, bias + 192, act + 3 * 5120, nullptr,          nullptr,          B);

    // backward: convT(l) with act_grad(t_{l-1}) gate fused in epilogue
    conv_kernel<true, 64, false><<<grid, blk>>>(B, 1.f, wb + 2 * WSZ, nullptr, act + 2 * 5120, T + 2ull * NCHW,  nullptr, A);
    conv_kernel<true, 64, false><<<grid, blk>>>(A, 1.f, wb + WSZ,     nullptr, act + 5120,     T + (size_t)NCHW, nullptr, B);
    conv_kernel<true, 64, false><<<grid, blk>>>(B, 1.f, wb,           nullptr, act,            T,                nullptr, A);

    // final convT (64->1) + combine
    final_kernel<<<grid, blk>>>(A, x, y, lam, (float*)d_out);
}